// round 12
// baseline (speedup 1.0000x reference)
#include <cuda_runtime.h>
#include <cuda_bf16.h>
#include <cfloat>
#include <math.h>
#include <cstdint>

// Problem constants
#define BB   16
#define SS   8192
#define AD   512
#define KD   512
#define MTOT (BB * SS)
#define NT   4          // 4 N-tiles of 128 cols

// ---------------------------------------------------------------------------
// Scratch globals
// ---------------------------------------------------------------------------
__device__ float         g_qp[BB * AD];
__device__ float         g_epart[NT * MTOT];
__device__ float         g_cpart[64 * BB * KD];
__device__ __nv_bfloat16 g_Bt_hi[AD * KD];    // n-major: [n][k] = hi(Wk[k][n])
__device__ __nv_bfloat16 g_Bt_lo[AD * KD];
__device__ __nv_bfloat16 g_Kc_hi[(size_t)BB * SS * KD];  // compacted keys hi
__device__ __nv_bfloat16 g_Kc_lo[(size_t)BB * SS * KD];  // compacted keys lo
__device__ int           g_rows[BB][SS];      // compacted active row indices
__device__ int           g_cnt[BB];           // active counts
__device__ float         g_acomp[BB][SS];     // compacted attention weights

// ---------------------------------------------------------------------------
// PTX helpers
// ---------------------------------------------------------------------------
__device__ __forceinline__ float tanh_fast(float x) {
    float y;
    asm("tanh.approx.f32 %0, %1;" : "=f"(y) : "f"(x));
    return y;
}
__device__ __forceinline__ uint32_t smem_u32(const void* p) {
    uint32_t a;
    asm("{ .reg .u64 t; cvta.to.shared.u64 t, %1; cvt.u32.u64 %0, t; }" : "=r"(a) : "l"(p));
    return a;
}
__device__ __forceinline__ void ldsm_x4(uint32_t* r, uint32_t addr) {
    asm volatile("ldmatrix.sync.aligned.m8n8.x4.shared.b16 {%0,%1,%2,%3}, [%4];"
                 : "=r"(r[0]), "=r"(r[1]), "=r"(r[2]), "=r"(r[3]) : "r"(addr));
}
__device__ __forceinline__ void mma16816(float* d, const uint32_t* a, const uint32_t* b) {
    asm volatile(
        "mma.sync.aligned.m16n8k16.row.col.f32.bf16.bf16.f32 "
        "{%0,%1,%2,%3}, {%4,%5,%6,%7}, {%8,%9}, {%0,%1,%2,%3};"
        : "+f"(d[0]), "+f"(d[1]), "+f"(d[2]), "+f"(d[3])
        : "r"(a[0]), "r"(a[1]), "r"(a[2]), "r"(a[3]), "r"(b[0]), "r"(b[1]));
}
#define CP_ASYNC16(dst, src) \
    asm volatile("cp.async.cg.shared.global [%0], [%1], 16;" :: "r"(dst), "l"(src) : "memory")
#define CP_COMMIT()  asm volatile("cp.async.commit_group;" ::: "memory")
#define CP_WAIT0()   asm volatile("cp.async.wait_group 0;" ::: "memory")
#define CP_WAIT1()   asm volatile("cp.async.wait_group 1;" ::: "memory")

// ---------------------------------------------------------------------------
// Kernel A: per-batch stable compaction of active rows (mask != 0)
// ---------------------------------------------------------------------------
__global__ __launch_bounds__(1024)
void compact_kernel(const int* __restrict__ mask) {
    const int b = blockIdx.x;
    const int t = threadIdx.x;
    const int lane = t & 31;
    const int wid  = t >> 5;
    __shared__ int wsum[32];
    __shared__ int s_total;

    int mv[8];
    int cnt = 0;
    const int base_row = t * 8;
    #pragma unroll
    for (int r = 0; r < 8; r++) {
        mv[r] = mask[b * SS + base_row + r];
        cnt += (mv[r] != 0);
    }
    int x = cnt;
    #pragma unroll
    for (int off = 1; off < 32; off <<= 1) {
        int y = __shfl_up_sync(0xffffffffu, x, off);
        if (lane >= off) x += y;
    }
    if (lane == 31) wsum[wid] = x;
    const int excl = x - cnt;
    __syncthreads();
    if (t == 0) {
        int run = 0;
        for (int i = 0; i < 32; i++) { int c = wsum[i]; wsum[i] = run; run += c; }
        s_total = run;
    }
    __syncthreads();
    int base = wsum[wid] + excl;
    #pragma unroll
    for (int r = 0; r < 8; r++)
        if (mv[r]) g_rows[b][base++] = base_row + r;
    const int total = s_total;
    if (t == 0) g_cnt[b] = total;
    for (int i = total + t; i < SS; i += 1024) g_rows[b][i] = 0;   // pad
}

// ---------------------------------------------------------------------------
// Kernel B: gather + split compacted keys rows to bf16 hi/lo
// ---------------------------------------------------------------------------
__global__ __launch_bounds__(256)
void prep_keys_kernel(const float* __restrict__ keys) {
    const int scn = blockIdx.x;     // 0..63 (128-slot chunks)
    const int b   = blockIdx.y;
    const int tofs = scn * 128;
    const int cnt = g_cnt[b];
    if (tofs >= cnt) return;

    for (int g = threadIdx.x; g < 128 * 64; g += 256) {   // granule = 8 floats
        const int r = g >> 6;
        const int i = tofs + r;
        if (i >= cnt) continue;
        const int col = (g & 63) * 8;
        const int row = g_rows[b][i];
        const float* src = keys + ((size_t)b * SS + row) * KD + col;
        float4 f0 = *(const float4*)(src);
        float4 f1 = *(const float4*)(src + 4);
        const float xs[8] = {f0.x, f0.y, f0.z, f0.w, f1.x, f1.y, f1.z, f1.w};
        uint4 hv, lv;
        __nv_bfloat162* hp = (__nv_bfloat162*)&hv;
        __nv_bfloat162* lp = (__nv_bfloat162*)&lv;
        #pragma unroll
        for (int p = 0; p < 4; p++) {
            const float x0 = xs[2 * p], x1 = xs[2 * p + 1];
            const __nv_bfloat16 h0 = __float2bfloat16(x0);
            const __nv_bfloat16 h1 = __float2bfloat16(x1);
            const __nv_bfloat16 l0 = __float2bfloat16(x0 - __bfloat162float(h0));
            const __nv_bfloat16 l1 = __float2bfloat16(x1 - __bfloat162float(h1));
            hp[p] = __nv_bfloat162(h0, h1);
            lp[p] = __nv_bfloat162(l0, l1);
        }
        const size_t dst = ((size_t)b * SS + i) * KD + col;
        *(uint4*)(g_Kc_hi + dst) = hv;
        *(uint4*)(g_Kc_lo + dst) = lv;
    }
}

// ---------------------------------------------------------------------------
// Kernel 0: prep Wk -> n-major bf16 hi/lo
// ---------------------------------------------------------------------------
__global__ void prep_wk_kernel(const float* __restrict__ Wk) {
    const int k = blockIdx.x;
    const int n = threadIdx.x;
    const float x = Wk[k * AD + n];
    const __nv_bfloat16 hi = __float2bfloat16(x);
    const __nv_bfloat16 lo = __float2bfloat16(x - __bfloat162float(hi));
    g_Bt_hi[n * KD + k] = hi;
    g_Bt_lo[n * KD + k] = lo;
}

// ---------------------------------------------------------------------------
// Kernel 1: q projection, split-K x4.  grid (BB, 8), block 256.
//   seg = 64 output cols; thread = (col within seg, k-group); smem-reduce.
// ---------------------------------------------------------------------------
__global__ __launch_bounds__(256)
void qproj_kernel(const float* __restrict__ query,
                  const float* __restrict__ Wq) {
    __shared__ float qs[AD];
    __shared__ float pred[4][64];
    const int b   = blockIdx.x;
    const int seg = blockIdx.y;          // 0..7
    const int t   = threadIdx.x;
    const int ci  = t & 63;              // col within segment
    const int kg  = t >> 6;              // 0..3  k-group of 128
    const int col = seg * 64 + ci;

    for (int i = t; i < AD; i += 256) qs[i] = query[b * AD + i];
    __syncthreads();

    float acc = 0.f;
    const float* wcol = Wq + (size_t)(kg * 128) * AD + col;
    #pragma unroll 8
    for (int j = 0; j < 128; j++)
        acc += qs[kg * 128 + j] * wcol[(size_t)j * AD];
    pred[kg][ci] = acc;
    __syncthreads();
    if (t < 64)
        g_qp[b * AD + col] = pred[0][ci] + pred[1][ci] + pred[2][ci] + pred[3][ci];
}

// ---------------------------------------------------------------------------
// Kernel 2: bf16 3-term GEMM, pure cp.async operands, 3-STAGE pipeline
//   128x128 block, 8 warps (2M x 4N), warp 64x32; ONE sync per chunk.
// ---------------------------------------------------------------------------
#define PADK 40                     // 80B row stride, ldmatrix conflict-free
#define ARR_B  (128 * PADK * 2)     // 10240 bytes per array
#define STG_B  (4 * ARR_B)          // 40960 bytes per stage
#define OFF_AH 0
#define OFF_AL ARR_B
#define OFF_BH (2 * ARR_B)
#define OFF_BL (3 * ARR_B)
#define SMEM_DYN (3 * STG_B)        // 122880; e_red overlays stage 0 after loop

__global__ __launch_bounds__(256)
void score_gemm_mma(const float* __restrict__ vvec) {
    extern __shared__ char smem[];
    const uint32_t sb = smem_u32(smem);

    const int tid = threadIdx.x;
    const int nt  = blockIdx.x;          // 0..3
    const int mt  = blockIdx.y;          // 0..1023
    const int b   = mt >> 6;
    const int tofs = (mt & 63) * 128;

    const int cnt = g_cnt[b];
    if (tofs >= cnt) return;

    const int wid = tid >> 5;
    const int lid = tid & 31;
    const int wm  = wid & 1;
    const int wn  = wid >> 1;

    // loader mapping: 512 granules (128 rows x 4 col-groups); 2 per thread
    const int g0row = tid >> 2,  g0c = (tid & 3) * 8;
    const int g1row = g0row + 64;

    const __nv_bfloat16* AcH = g_Kc_hi + ((size_t)b * SS + tofs) * KD;
    const __nv_bfloat16* AcL = g_Kc_lo + ((size_t)b * SS + tofs) * KD;
    const __nv_bfloat16* BtH = g_Bt_hi + (size_t)(nt * 128) * KD;
    const __nv_bfloat16* BtL = g_Bt_lo + (size_t)(nt * 128) * KD;

    const uint32_t st0 = (uint32_t)(g0row * PADK + g0c) * 2;
    const uint32_t st1 = (uint32_t)(g1row * PADK + g0c) * 2;

    auto issue = [&](int kc) {
        const int ko = kc * 32;
        const uint32_t stg = sb + (uint32_t)(kc % 3) * STG_B;
        CP_ASYNC16(stg + OFF_AH + st0, AcH + (size_t)g0row * KD + ko + g0c);
        CP_ASYNC16(stg + OFF_AH + st1, AcH + (size_t)g1row * KD + ko + g0c);
        CP_ASYNC16(stg + OFF_AL + st0, AcL + (size_t)g0row * KD + ko + g0c);
        CP_ASYNC16(stg + OFF_AL + st1, AcL + (size_t)g1row * KD + ko + g0c);
        CP_ASYNC16(stg + OFF_BH + st0, BtH + (size_t)g0row * KD + ko + g0c);
        CP_ASYNC16(stg + OFF_BH + st1, BtH + (size_t)g1row * KD + ko + g0c);
        CP_ASYNC16(stg + OFF_BL + st0, BtL + (size_t)g0row * KD + ko + g0c);
        CP_ASYNC16(stg + OFF_BL + st1, BtL + (size_t)g1row * KD + ko + g0c);
        CP_COMMIT();
    };

    float acc[4][4][4];
    #pragma unroll
    for (int i = 0; i < 4; i++)
        #pragma unroll
        for (int j = 0; j < 4; j++)
            #pragma unroll
            for (int e = 0; e < 4; e++) acc[i][j][e] = 0.f;

    // fragment address components
    const int arow  = wm * 64 + (lid & 15);
    const int acolh = (lid >> 4) << 3;
    const int brow  = wn * 32 + ((lid >> 4) << 3) + (lid & 7);
    const int bcolh = ((lid >> 3) & 1) << 3;

    issue(0);
    issue(1);

    for (int kc = 0; kc < 16; kc++) {
        // stage kc must be resident: allow at most 1 younger group in flight
        if (kc + 1 < 16) { CP_WAIT1(); } else { CP_WAIT0(); }
        __syncthreads();                         // single barrier per chunk

        const uint32_t stg = sb + (uint32_t)(kc % 3) * STG_B;
        const uint32_t sAh = stg + OFF_AH;
        const uint32_t sAl = stg + OFF_AL;
        const uint32_t sBh = stg + OFF_BH;
        const uint32_t sBl = stg + OFF_BL;

        #pragma unroll
        for (int ks = 0; ks < 2; ks++) {
            const int kb = ks * 16;
            uint32_t ah[4][4], al[4][4];
            #pragma unroll
            for (int mf = 0; mf < 4; mf++) {
                const uint32_t off = (uint32_t)(((arow + mf * 16) * PADK + kb + acolh) * 2);
                ldsm_x4(ah[mf], sAh + off);
                ldsm_x4(al[mf], sAl + off);
            }
            uint32_t bh[4][2], bl[4][2];
            #pragma unroll
            for (int nf2 = 0; nf2 < 2; nf2++) {
                const uint32_t off = (uint32_t)(((brow + nf2 * 16) * PADK + kb + bcolh) * 2);
                uint32_t t[4];
                ldsm_x4(t, sBh + off);
                bh[2 * nf2][0] = t[0]; bh[2 * nf2][1] = t[1];
                bh[2 * nf2 + 1][0] = t[2]; bh[2 * nf2 + 1][1] = t[3];
                ldsm_x4(t, sBl + off);
                bl[2 * nf2][0] = t[0]; bl[2 * nf2][1] = t[1];
                bl[2 * nf2 + 1][0] = t[2]; bl[2 * nf2 + 1][1] = t[3];
            }
            #pragma unroll
            for (int mf = 0; mf < 4; mf++)
                #pragma unroll
                for (int nf = 0; nf < 4; nf++) {
                    mma16816(acc[mf][nf], ah[mf], bh[nf]);
                    mma16816(acc[mf][nf], al[mf], bh[nf]);
                    mma16816(acc[mf][nf], ah[mf], bl[nf]);
                }
        }

        // fill the stage 2 ahead (disjoint from current and laggard stages)
        if (kc + 2 < 16) issue(kc + 2);
    }

    // ---- epilogue: e_partial[row] = sum over this block's 128 cols ----
    float qv[4][2], vv[4][2];
    #pragma unroll
    for (int nf = 0; nf < 4; nf++)
        #pragma unroll
        for (int j = 0; j < 2; j++) {
            const int col = nt * 128 + wn * 32 + nf * 8 + (lid & 3) * 2 + j;
            qv[nf][j] = g_qp[b * AD + col];
            vv[nf][j] = vvec[col];
        }

    float es[4][2];
    #pragma unroll
    for (int mf = 0; mf < 4; mf++)
        #pragma unroll
        for (int h = 0; h < 2; h++) {
            float s = 0.f;
            #pragma unroll
            for (int nf = 0; nf < 4; nf++) {
                s += tanh_fast(acc[mf][nf][2 * h + 0] + qv[nf][0]) * vv[nf][0];
                s += tanh_fast(acc[mf][nf][2 * h + 1] + qv[nf][1]) * vv[nf][1];
            }
            es[mf][h] = s;
        }
    #pragma unroll
    for (int off = 1; off <= 2; off <<= 1)
        #pragma unroll
        for (int mf = 0; mf < 4; mf++)
            #pragma unroll
            for (int h = 0; h < 2; h++)
                es[mf][h] += __shfl_xor_sync(0xffffffffu, es[mf][h], off);

    __syncthreads();                                 // everyone done with MMA stages
    float (*e_red)[128] = (float (*)[128])(smem);    // overlay stage 0
    if ((lid & 3) == 0) {
        const int gq = lid >> 2;
        #pragma unroll
        for (int mf = 0; mf < 4; mf++)
            #pragma unroll
            for (int h = 0; h < 2; h++)
                e_red[wn][wm * 64 + mf * 16 + h * 8 + gq] = es[mf][h];
    }
    __syncthreads();
    if (tid < 128)
        g_epart[nt * MTOT + b * SS + tofs + tid] =
            e_red[0][tid] + e_red[1][tid] + e_red[2][tid] + e_red[3][tid];
}

// ---------------------------------------------------------------------------
// Kernel 3: softmax over compacted scores; scatter a + zero masked slots
// ---------------------------------------------------------------------------
__global__ __launch_bounds__(1024)
void softmax_kernel(const int* __restrict__ mask, float* __restrict__ out) {
    const int b = blockIdx.x;
    const int t = threadIdx.x;
    const int lane = t & 31;
    const int wid  = t >> 5;
    __shared__ float sred[32];

    const int cnt = g_cnt[b];

    float sc[8];
    #pragma unroll
    for (int r = 0; r < 8; r++) {
        const int i = t + r * 1024;
        float e = -FLT_MAX;
        if (i < cnt) {
            e = 0.f;
            #pragma unroll
            for (int p = 0; p < NT; p++)
                e += g_epart[p * MTOT + b * SS + i];
        }
        sc[r] = e;
    }

    float m = sc[0];
    #pragma unroll
    for (int r = 1; r < 8; r++) m = fmaxf(m, sc[r]);
    #pragma unroll
    for (int off = 16; off > 0; off >>= 1)
        m = fmaxf(m, __shfl_xor_sync(0xffffffffu, m, off));
    if (lane == 0) sred[wid] = m;
    __syncthreads();
    if (t < 32) {
        float x = sred[t];
        #pragma unroll
        for (int off = 16; off > 0; off >>= 1)
            x = fmaxf(x, __shfl_xor_sync(0xffffffffu, x, off));
        if (t == 0) sred[0] = x;
    }
    __syncthreads();
    m = sred[0];
    __syncthreads();

    float ex[8];
    float sum = 0.f;
    #pragma unroll
    for (int r = 0; r < 8; r++) {
        ex[r] = expf(sc[r] - m);
        sum += ex[r];
    }
    #pragma unroll
    for (int off = 16; off > 0; off >>= 1)
        sum += __shfl_xor_sync(0xffffffffu, sum, off);
    if (lane == 0) sred[wid] = sum;
    __syncthreads();
    if (t < 32) {
        float x = sred[t];
        #pragma unroll
        for (int off = 16; off > 0; off >>= 1)
            x += __shfl_xor_sync(0xffffffffu, x, off);
        if (t == 0) sred[0] = x;
    }
    __syncthreads();
    const float inv = 1.f / sred[0];

    #pragma unroll
    for (int r = 0; r < 8; r++) {
        const int i = t + r * 1024;
        const float av = (i < cnt) ? ex[r] * inv : 0.f;
        g_acomp[b][i] = av;
        if (i < cnt) out[BB * KD + b * SS + g_rows[b][i]] = av;
        if (mask[b * SS + i] == 0) out[BB * KD + b * SS + i] = 0.f;
    }
}

// ---------------------------------------------------------------------------
// Kernel 4: context partials over compacted rows (gathered keys)
// ---------------------------------------------------------------------------
__global__ __launch_bounds__(256)
void ctx_part_kernel(const float* __restrict__ keys) {
    const int scn = blockIdx.x;
    const int b   = blockIdx.y;
    const int t   = threadIdx.x;

    if (scn * 128 >= g_cnt[b]) {
        g_cpart[(scn * BB + b) * KD + t]       = 0.f;
        g_cpart[(scn * BB + b) * KD + t + 256] = 0.f;
        return;
    }

    __shared__ float as[128];
    __shared__ int   rs[128];
    if (t < 128) {
        as[t] = g_acomp[b][scn * 128 + t];
        rs[t] = g_rows[b][scn * 128 + t];
    }
    __syncthreads();

    const float* kb = keys + (size_t)b * SS * KD;
    float s0 = 0.f, s1 = 0.f;
    #pragma unroll 4
    for (int s = 0; s < 128; s++) {
        const float av = as[s];
        const float* kr = kb + (size_t)rs[s] * KD;
        s0 += av * kr[t];
        s1 += av * kr[t + 256];
    }
    g_cpart[(scn * BB + b) * KD + t]       = s0;
    g_cpart[(scn * BB + b) * KD + t + 256] = s1;
}

// ---------------------------------------------------------------------------
// Kernel 5: reduce context partials
// ---------------------------------------------------------------------------
__global__ __launch_bounds__(512)
void ctx_reduce_kernel(float* __restrict__ out) {
    const int b = blockIdx.x;
    const int t = threadIdx.x;
    float s = 0.f;
    #pragma unroll 8
    for (int scn = 0; scn < 64; scn++)
        s += g_cpart[(scn * BB + b) * KD + t];
    out[b * KD + t] = s;
}

// ---------------------------------------------------------------------------
extern "C" void kernel_launch(void* const* d_in, const int* in_sizes, int n_in,
                              void* d_out, int out_size) {
    const float* query = (const float*)d_in[0];
    const float* keys  = (const float*)d_in[1];
    const int*   mask  = (const int*)  d_in[2];
    const float* Wq    = (const float*)d_in[3];
    const float* Wk    = (const float*)d_in[4];
    const float* v     = (const float*)d_in[5];
    float* out = (float*)d_out;

    static bool attr_set = false;
    if (!attr_set) {
        cudaFuncSetAttribute(score_gemm_mma,
                             cudaFuncAttributeMaxDynamicSharedMemorySize, SMEM_DYN);
        attr_set = true;
    }

    compact_kernel<<<BB, 1024>>>(mask);
    prep_keys_kernel<<<dim3(64, BB), 256>>>(keys);
    prep_wk_kernel<<<KD, AD>>>(Wk);
    qproj_kernel<<<dim3(BB, 8), 256>>>(query, Wq);
    score_gemm_mma<<<dim3(NT, 1024), 256, SMEM_DYN>>>(v);
    softmax_kernel<<<BB, 1024>>>(mask, out);
    ctx_part_kernel<<<dim3(64, BB), 256>>>(keys);
    ctx_reduce_kernel<<<BB, 512>>>(out);
}

// round 13
// speedup vs baseline: 1.0887x; 1.0887x over previous
#include <cuda_runtime.h>
#include <cuda_bf16.h>
#include <cfloat>
#include <math.h>
#include <cstdint>

// Problem constants
#define BB   16
#define SS   8192
#define AD   512
#define KD   512
#define MTOT (BB * SS)
#define NT   4          // 4 N-tiles of 128 cols

// ---------------------------------------------------------------------------
// Scratch globals
// ---------------------------------------------------------------------------
__device__ float         g_qp[BB * AD];
__device__ float         g_epart[NT * MTOT];
__device__ float         g_cpart[64 * BB * KD];
__device__ __nv_bfloat16 g_Bt_hi[AD * KD];    // n-major: [n][k] = hi(Wk[k][n])
__device__ __nv_bfloat16 g_Bt_lo[AD * KD];
__device__ __nv_bfloat16 g_Kc_hi[(size_t)BB * SS * KD];  // compacted keys hi
__device__ __nv_bfloat16 g_Kc_lo[(size_t)BB * SS * KD];  // compacted keys lo
__device__ int           g_rows[BB][SS];      // compacted active row indices
__device__ int           g_cnt[BB];           // active counts
__device__ float         g_acomp[BB][SS];     // compacted attention weights

// ---------------------------------------------------------------------------
// PTX helpers
// ---------------------------------------------------------------------------
__device__ __forceinline__ float tanh_fast(float x) {
    float y;
    asm("tanh.approx.f32 %0, %1;" : "=f"(y) : "f"(x));
    return y;
}
__device__ __forceinline__ uint32_t smem_u32(const void* p) {
    uint32_t a;
    asm("{ .reg .u64 t; cvta.to.shared.u64 t, %1; cvt.u32.u64 %0, t; }" : "=r"(a) : "l"(p));
    return a;
}
__device__ __forceinline__ void ldsm_x4(uint32_t* r, uint32_t addr) {
    asm volatile("ldmatrix.sync.aligned.m8n8.x4.shared.b16 {%0,%1,%2,%3}, [%4];"
                 : "=r"(r[0]), "=r"(r[1]), "=r"(r[2]), "=r"(r[3]) : "r"(addr));
}
__device__ __forceinline__ void mma16816(float* d, const uint32_t* a, const uint32_t* b) {
    asm volatile(
        "mma.sync.aligned.m16n8k16.row.col.f32.bf16.bf16.f32 "
        "{%0,%1,%2,%3}, {%4,%5,%6,%7}, {%8,%9}, {%0,%1,%2,%3};"
        : "+f"(d[0]), "+f"(d[1]), "+f"(d[2]), "+f"(d[3])
        : "r"(a[0]), "r"(a[1]), "r"(a[2]), "r"(a[3]), "r"(b[0]), "r"(b[1]));
}
#define CP_ASYNC16(dst, src) \
    asm volatile("cp.async.cg.shared.global [%0], [%1], 16;" :: "r"(dst), "l"(src) : "memory")
#define CP_COMMIT()  asm volatile("cp.async.commit_group;" ::: "memory")
#define CP_WAIT0()   asm volatile("cp.async.wait_group 0;" ::: "memory")

// ---------------------------------------------------------------------------
// Kernel A: per-batch stable compaction of active rows (mask != 0)
// ---------------------------------------------------------------------------
__global__ __launch_bounds__(1024)
void compact_kernel(const int* __restrict__ mask) {
    const int b = blockIdx.x;
    const int t = threadIdx.x;
    const int lane = t & 31;
    const int wid  = t >> 5;
    __shared__ int wsum[32];
    __shared__ int s_total;

    int mv[8];
    int cnt = 0;
    const int base_row = t * 8;
    #pragma unroll
    for (int r = 0; r < 8; r++) {
        mv[r] = mask[b * SS + base_row + r];
        cnt += (mv[r] != 0);
    }
    int x = cnt;
    #pragma unroll
    for (int off = 1; off < 32; off <<= 1) {
        int y = __shfl_up_sync(0xffffffffu, x, off);
        if (lane >= off) x += y;
    }
    if (lane == 31) wsum[wid] = x;
    const int excl = x - cnt;
    __syncthreads();
    if (t == 0) {
        int run = 0;
        for (int i = 0; i < 32; i++) { int c = wsum[i]; wsum[i] = run; run += c; }
        s_total = run;
    }
    __syncthreads();
    int base = wsum[wid] + excl;
    #pragma unroll
    for (int r = 0; r < 8; r++)
        if (mv[r]) g_rows[b][base++] = base_row + r;
    const int total = s_total;
    if (t == 0) g_cnt[b] = total;
    for (int i = total + t; i < SS; i += 1024) g_rows[b][i] = 0;   // pad
}

// ---------------------------------------------------------------------------
// Fused prep kernel: grid-partitioned independent work.
//   blocks [0, 1024)          : prep_keys (gather + hi/lo split)
//   blocks [1024, 1152)       : qproj (split-K x4)
//   blocks [1152, 1664)       : prep_wk (transpose + hi/lo split)
// 256 threads each; latency-bound qproj blocks hide under memory-bound ones.
// ---------------------------------------------------------------------------
__global__ __launch_bounds__(256)
void prep_fused_kernel(const float* __restrict__ keys,
                       const float* __restrict__ query,
                       const float* __restrict__ Wq,
                       const float* __restrict__ Wk) {
    const int blk = blockIdx.x;
    const int t   = threadIdx.x;

    if (blk < 1024) {
        // ---------------- prep_keys ----------------
        const int scn = blk & 63;
        const int b   = blk >> 6;
        const int tofs = scn * 128;
        const int cnt = g_cnt[b];
        if (tofs >= cnt) return;

        for (int g = t; g < 128 * 64; g += 256) {   // granule = 8 floats
            const int r = g >> 6;
            const int i = tofs + r;
            if (i >= cnt) continue;
            const int col = (g & 63) * 8;
            const int row = g_rows[b][i];
            const float* src = keys + ((size_t)b * SS + row) * KD + col;
            float4 f0 = *(const float4*)(src);
            float4 f1 = *(const float4*)(src + 4);
            const float xs[8] = {f0.x, f0.y, f0.z, f0.w, f1.x, f1.y, f1.z, f1.w};
            uint4 hv, lv;
            __nv_bfloat162* hp = (__nv_bfloat162*)&hv;
            __nv_bfloat162* lp = (__nv_bfloat162*)&lv;
            #pragma unroll
            for (int p = 0; p < 4; p++) {
                const float x0 = xs[2 * p], x1 = xs[2 * p + 1];
                const __nv_bfloat16 h0 = __float2bfloat16(x0);
                const __nv_bfloat16 h1 = __float2bfloat16(x1);
                const __nv_bfloat16 l0 = __float2bfloat16(x0 - __bfloat162float(h0));
                const __nv_bfloat16 l1 = __float2bfloat16(x1 - __bfloat162float(h1));
                hp[p] = __nv_bfloat162(h0, h1);
                lp[p] = __nv_bfloat162(l0, l1);
            }
            const size_t dst = ((size_t)b * SS + i) * KD + col;
            *(uint4*)(g_Kc_hi + dst) = hv;
            *(uint4*)(g_Kc_lo + dst) = lv;
        }
    } else if (blk < 1152) {
        // ---------------- qproj ----------------
        __shared__ float qs[AD];
        __shared__ float pred[4][64];
        const int q   = blk - 1024;
        const int b   = q >> 3;              // 0..15
        const int seg = q & 7;               // 0..7
        const int ci  = t & 63;
        const int kg  = t >> 6;
        const int col = seg * 64 + ci;

        for (int i = t; i < AD; i += 256) qs[i] = query[b * AD + i];
        __syncthreads();

        float acc = 0.f;
        const float* wcol = Wq + (size_t)(kg * 128) * AD + col;
        #pragma unroll 16
        for (int j = 0; j < 128; j++)
            acc += qs[kg * 128 + j] * wcol[(size_t)j * AD];
        pred[kg][ci] = acc;
        __syncthreads();
        if (t < 64)
            g_qp[b * AD + col] = pred[0][ci] + pred[1][ci] + pred[2][ci] + pred[3][ci];
    } else {
        // ---------------- prep_wk ----------------
        const int k = blk - 1152;            // 0..511
        for (int n = t; n < AD; n += 256) {
            const float x = Wk[k * AD + n];
            const __nv_bfloat16 hi = __float2bfloat16(x);
            const __nv_bfloat16 lo = __float2bfloat16(x - __bfloat162float(hi));
            g_Bt_hi[n * KD + k] = hi;
            g_Bt_lo[n * KD + k] = lo;
        }
    }
}

// ---------------------------------------------------------------------------
// Kernel 2: bf16 3-term GEMM, cp.async operands, SINGLE-stage smem,
//   2 CTAs/SM (sibling CTA's MMA hides this CTA's fill phase).
//   128x128 block, 8 warps (2M x 4N), warp 64x32; A-frags loaded per-mf.
// ---------------------------------------------------------------------------
#define PADK 40                     // 80B row stride, ldmatrix conflict-free
#define ARR_B  (128 * PADK * 2)     // 10240 bytes per array
#define OFF_AH 0
#define OFF_AL ARR_B
#define OFF_BH (2 * ARR_B)
#define OFF_BL (3 * ARR_B)
#define SMEM_DYN (4 * ARR_B)        // 40960 per CTA; e_red overlays after loop

__global__ __launch_bounds__(256, 2)
void score_gemm_mma(const float* __restrict__ vvec) {
    extern __shared__ char smem[];
    const uint32_t sb = smem_u32(smem);

    const int tid = threadIdx.x;
    const int nt  = blockIdx.x;          // 0..3
    const int mt  = blockIdx.y;          // 0..1023
    const int b   = mt >> 6;
    const int tofs = (mt & 63) * 128;

    const int cnt = g_cnt[b];
    if (tofs >= cnt) return;

    const int wid = tid >> 5;
    const int lid = tid & 31;
    const int wm  = wid & 1;
    const int wn  = wid >> 1;

    // loader mapping: 512 granules per array (128 rows x 4 col-groups); 2/thread
    const int g0row = tid >> 2,  g0c = (tid & 3) * 8;
    const int g1row = g0row + 64;

    const __nv_bfloat16* AcH = g_Kc_hi + ((size_t)b * SS + tofs) * KD;
    const __nv_bfloat16* AcL = g_Kc_lo + ((size_t)b * SS + tofs) * KD;
    const __nv_bfloat16* BtH = g_Bt_hi + (size_t)(nt * 128) * KD;
    const __nv_bfloat16* BtL = g_Bt_lo + (size_t)(nt * 128) * KD;

    const uint32_t st0 = (uint32_t)(g0row * PADK + g0c) * 2;
    const uint32_t st1 = (uint32_t)(g1row * PADK + g0c) * 2;

    float acc[4][4][4];
    #pragma unroll
    for (int i = 0; i < 4; i++)
        #pragma unroll
        for (int j = 0; j < 4; j++)
            #pragma unroll
            for (int e = 0; e < 4; e++) acc[i][j][e] = 0.f;

    // fragment address components
    const int arow  = wm * 64 + (lid & 15);
    const int acolh = (lid >> 4) << 3;
    const int brow  = wn * 32 + ((lid >> 4) << 3) + (lid & 7);
    const int bcolh = ((lid >> 3) & 1) << 3;

    const uint32_t sAh = sb + OFF_AH;
    const uint32_t sAl = sb + OFF_AL;
    const uint32_t sBh = sb + OFF_BH;
    const uint32_t sBl = sb + OFF_BL;

    for (int kc = 0; kc < 16; kc++) {
        const int ko = kc * 32;
        // ---- fill single stage via cp.async (8 x 16B per thread) ----
        CP_ASYNC16(sAh + st0, AcH + (size_t)g0row * KD + ko + g0c);
        CP_ASYNC16(sAh + st1, AcH + (size_t)g1row * KD + ko + g0c);
        CP_ASYNC16(sAl + st0, AcL + (size_t)g0row * KD + ko + g0c);
        CP_ASYNC16(sAl + st1, AcL + (size_t)g1row * KD + ko + g0c);
        CP_ASYNC16(sBh + st0, BtH + (size_t)g0row * KD + ko + g0c);
        CP_ASYNC16(sBh + st1, BtH + (size_t)g1row * KD + ko + g0c);
        CP_ASYNC16(sBl + st0, BtL + (size_t)g0row * KD + ko + g0c);
        CP_ASYNC16(sBl + st1, BtL + (size_t)g1row * KD + ko + g0c);
        CP_COMMIT();
        CP_WAIT0();
        __syncthreads();                 // stage filled

        // ---- MMAs: 2 k-steps of k16; B frags resident, A frags per-mf ----
        #pragma unroll
        for (int ks = 0; ks < 2; ks++) {
            const int kb = ks * 16;
            uint32_t bh[4][2], bl[4][2];
            #pragma unroll
            for (int nf2 = 0; nf2 < 2; nf2++) {
                const uint32_t off = (uint32_t)(((brow + nf2 * 16) * PADK + kb + bcolh) * 2);
                uint32_t u[4];
                ldsm_x4(u, sBh + off);
                bh[2 * nf2][0] = u[0]; bh[2 * nf2][1] = u[1];
                bh[2 * nf2 + 1][0] = u[2]; bh[2 * nf2 + 1][1] = u[3];
                ldsm_x4(u, sBl + off);
                bl[2 * nf2][0] = u[0]; bl[2 * nf2][1] = u[1];
                bl[2 * nf2 + 1][0] = u[2]; bl[2 * nf2 + 1][1] = u[3];
            }
            #pragma unroll
            for (int mf = 0; mf < 4; mf++) {
                uint32_t ah[4], al[4];
                const uint32_t off = (uint32_t)(((arow + mf * 16) * PADK + kb + acolh) * 2);
                ldsm_x4(ah, sAh + off);
                ldsm_x4(al, sAl + off);
                #pragma unroll
                for (int nf = 0; nf < 4; nf++) {
                    mma16816(acc[mf][nf], ah, bh[nf]);
                    mma16816(acc[mf][nf], al, bh[nf]);
                    mma16816(acc[mf][nf], ah, bl[nf]);
                }
            }
        }
        __syncthreads();                 // all warps done before refill
    }

    // ---- epilogue: e_partial[row] = sum over this block's 128 cols ----
    float qv[4][2], vv[4][2];
    #pragma unroll
    for (int nf = 0; nf < 4; nf++)
        #pragma unroll
        for (int j = 0; j < 2; j++) {
            const int col = nt * 128 + wn * 32 + nf * 8 + (lid & 3) * 2 + j;
            qv[nf][j] = g_qp[b * AD + col];
            vv[nf][j] = vvec[col];
        }

    float es[4][2];
    #pragma unroll
    for (int mf = 0; mf < 4; mf++)
        #pragma unroll
        for (int h = 0; h < 2; h++) {
            float s = 0.f;
            #pragma unroll
            for (int nf = 0; nf < 4; nf++) {
                s += tanh_fast(acc[mf][nf][2 * h + 0] + qv[nf][0]) * vv[nf][0];
                s += tanh_fast(acc[mf][nf][2 * h + 1] + qv[nf][1]) * vv[nf][1];
            }
            es[mf][h] = s;
        }
    #pragma unroll
    for (int off = 1; off <= 2; off <<= 1)
        #pragma unroll
        for (int mf = 0; mf < 4; mf++)
            #pragma unroll
            for (int h = 0; h < 2; h++)
                es[mf][h] += __shfl_xor_sync(0xffffffffu, es[mf][h], off);

    float (*e_red)[128] = (float (*)[128])(smem);    // overlay stage (free now)
    if ((lid & 3) == 0) {
        const int gq = lid >> 2;
        #pragma unroll
        for (int mf = 0; mf < 4; mf++)
            #pragma unroll
            for (int h = 0; h < 2; h++)
                e_red[wn][wm * 64 + mf * 16 + h * 8 + gq] = es[mf][h];
    }
    __syncthreads();
    if (tid < 128)
        g_epart[nt * MTOT + b * SS + tofs + tid] =
            e_red[0][tid] + e_red[1][tid] + e_red[2][tid] + e_red[3][tid];
}

// ---------------------------------------------------------------------------
// Kernel 3: softmax over compacted scores; scatter a + zero masked slots
// ---------------------------------------------------------------------------
__global__ __launch_bounds__(1024)
void softmax_kernel(const int* __restrict__ mask, float* __restrict__ out) {
    const int b = blockIdx.x;
    const int t = threadIdx.x;
    const int lane = t & 31;
    const int wid  = t >> 5;
    __shared__ float sred[32];

    const int cnt = g_cnt[b];

    float sc[8];
    #pragma unroll
    for (int r = 0; r < 8; r++) {
        const int i = t + r * 1024;
        float e = -FLT_MAX;
        if (i < cnt) {
            e = 0.f;
            #pragma unroll
            for (int p = 0; p < NT; p++)
                e += g_epart[p * MTOT + b * SS + i];
        }
        sc[r] = e;
    }

    float m = sc[0];
    #pragma unroll
    for (int r = 1; r < 8; r++) m = fmaxf(m, sc[r]);
    #pragma unroll
    for (int off = 16; off > 0; off >>= 1)
        m = fmaxf(m, __shfl_xor_sync(0xffffffffu, m, off));
    if (lane == 0) sred[wid] = m;
    __syncthreads();
    if (t < 32) {
        float x = sred[t];
        #pragma unroll
        for (int off = 16; off > 0; off >>= 1)
            x = fmaxf(x, __shfl_xor_sync(0xffffffffu, x, off));
        if (t == 0) sred[0] = x;
    }
    __syncthreads();
    m = sred[0];
    __syncthreads();

    float ex[8];
    float sum = 0.f;
    #pragma unroll
    for (int r = 0; r < 8; r++) {
        ex[r] = expf(sc[r] - m);
        sum += ex[r];
    }
    #pragma unroll
    for (int off = 16; off > 0; off >>= 1)
        sum += __shfl_xor_sync(0xffffffffu, sum, off);
    if (lane == 0) sred[wid] = sum;
    __syncthreads();
    if (t < 32) {
        float x = sred[t];
        #pragma unroll
        for (int off = 16; off > 0; off >>= 1)
            x += __shfl_xor_sync(0xffffffffu, x, off);
        if (t == 0) sred[0] = x;
    }
    __syncthreads();
    const float inv = 1.f / sred[0];

    #pragma unroll
    for (int r = 0; r < 8; r++) {
        const int i = t + r * 1024;
        const float av = (i < cnt) ? ex[r] * inv : 0.f;
        g_acomp[b][i] = av;
        if (i < cnt) out[BB * KD + b * SS + g_rows[b][i]] = av;
        if (mask[b * SS + i] == 0) out[BB * KD + b * SS + i] = 0.f;
    }
}

// ---------------------------------------------------------------------------
// Kernel 4: context partials over compacted rows (gathered keys)
// ---------------------------------------------------------------------------
__global__ __launch_bounds__(256)
void ctx_part_kernel(const float* __restrict__ keys) {
    const int scn = blockIdx.x;
    const int b   = blockIdx.y;
    const int t   = threadIdx.x;

    if (scn * 128 >= g_cnt[b]) {
        g_cpart[(scn * BB + b) * KD + t]       = 0.f;
        g_cpart[(scn * BB + b) * KD + t + 256] = 0.f;
        return;
    }

    __shared__ float as[128];
    __shared__ int   rs[128];
    if (t < 128) {
        as[t] = g_acomp[b][scn * 128 + t];
        rs[t] = g_rows[b][scn * 128 + t];
    }
    __syncthreads();

    const float* kb = keys + (size_t)b * SS * KD;
    float s0 = 0.f, s1 = 0.f;
    #pragma unroll 4
    for (int s = 0; s < 128; s++) {
        const float av = as[s];
        const float* kr = kb + (size_t)rs[s] * KD;
        s0 += av * kr[t];
        s1 += av * kr[t + 256];
    }
    g_cpart[(scn * BB + b) * KD + t]       = s0;
    g_cpart[(scn * BB + b) * KD + t + 256] = s1;
}

// ---------------------------------------------------------------------------
// Kernel 5: reduce context partials
// ---------------------------------------------------------------------------
__global__ __launch_bounds__(512)
void ctx_reduce_kernel(float* __restrict__ out) {
    const int b = blockIdx.x;
    const int t = threadIdx.x;
    float s = 0.f;
    #pragma unroll 8
    for (int scn = 0; scn < 64; scn++)
        s += g_cpart[(scn * BB + b) * KD + t];
    out[b * KD + t] = s;
}

// ---------------------------------------------------------------------------
extern "C" void kernel_launch(void* const* d_in, const int* in_sizes, int n_in,
                              void* d_out, int out_size) {
    const float* query = (const float*)d_in[0];
    const float* keys  = (const float*)d_in[1];
    const int*   mask  = (const int*)  d_in[2];
    const float* Wq    = (const float*)d_in[3];
    const float* Wk    = (const float*)d_in[4];
    const float* v     = (const float*)d_in[5];
    float* out = (float*)d_out;

    static bool attr_set = false;
    if (!attr_set) {
        cudaFuncSetAttribute(score_gemm_mma,
                             cudaFuncAttributeMaxDynamicSharedMemorySize, SMEM_DYN);
        attr_set = true;
    }

    compact_kernel<<<BB, 1024>>>(mask);
    prep_fused_kernel<<<1664, 256>>>(keys, query, Wq, Wk);
    score_gemm_mma<<<dim3(NT, 1024), 256, SMEM_DYN>>>(v);
    softmax_kernel<<<BB, 1024>>>(mask, out);
    ctx_part_kernel<<<dim3(64, BB), 256>>>(keys);
    ctx_reduce_kernel<<<BB, 512>>>(out);
}

// round 14
// speedup vs baseline: 1.2145x; 1.1155x over previous
#include <cuda_runtime.h>
#include <cuda_bf16.h>
#include <cfloat>
#include <math.h>
#include <cstdint>

// Problem constants
#define BB   16
#define SS   8192
#define AD   512
#define KD   512
#define MTOT (BB * SS)
#define NT   4          // 4 N-tiles of 128 cols

// ---------------------------------------------------------------------------
// Scratch globals
// ---------------------------------------------------------------------------
__device__ float         g_qp[BB * AD];
__device__ float         g_epart[NT * MTOT];
__device__ float         g_cpart[64 * BB * KD];
__device__ __nv_bfloat16 g_Bt_hi[AD * KD];    // n-major: [n][k] = hi(Wk[k][n])
__device__ __nv_bfloat16 g_Bt_lo[AD * KD];
__device__ int           g_rows[BB][SS];      // compacted active row indices
__device__ int           g_cnt[BB];           // active counts
__device__ float         g_acomp[BB][SS];     // compacted attention weights

// ---------------------------------------------------------------------------
// PTX helpers
// ---------------------------------------------------------------------------
__device__ __forceinline__ float tanh_fast(float x) {
    float y;
    asm("tanh.approx.f32 %0, %1;" : "=f"(y) : "f"(x));
    return y;
}
__device__ __forceinline__ uint32_t smem_u32(const void* p) {
    uint32_t a;
    asm("{ .reg .u64 t; cvta.to.shared.u64 t, %1; cvt.u32.u64 %0, t; }" : "=r"(a) : "l"(p));
    return a;
}
__device__ __forceinline__ void ldsm_x4(uint32_t* r, uint32_t addr) {
    asm volatile("ldmatrix.sync.aligned.m8n8.x4.shared.b16 {%0,%1,%2,%3}, [%4];"
                 : "=r"(r[0]), "=r"(r[1]), "=r"(r[2]), "=r"(r[3]) : "r"(addr));
}
__device__ __forceinline__ void mma16816(float* d, const uint32_t* a, const uint32_t* b) {
    asm volatile(
        "mma.sync.aligned.m16n8k16.row.col.f32.bf16.bf16.f32 "
        "{%0,%1,%2,%3}, {%4,%5,%6,%7}, {%8,%9}, {%0,%1,%2,%3};"
        : "+f"(d[0]), "+f"(d[1]), "+f"(d[2]), "+f"(d[3])
        : "r"(a[0]), "r"(a[1]), "r"(a[2]), "r"(a[3]), "r"(b[0]), "r"(b[1]));
}
#define CP_ASYNC16(dst, src) \
    asm volatile("cp.async.cg.shared.global [%0], [%1], 16;" :: "r"(dst), "l"(src) : "memory")
#define CP_COMMIT()  asm volatile("cp.async.commit_group;" ::: "memory")
#define CP_WAIT0()   asm volatile("cp.async.wait_group 0;" ::: "memory")

// ---------------------------------------------------------------------------
// Kernel A: per-batch stable compaction of active rows (mask != 0)
// ---------------------------------------------------------------------------
__global__ __launch_bounds__(1024)
void compact_kernel(const int* __restrict__ mask) {
    const int b = blockIdx.x;
    const int t = threadIdx.x;
    const int lane = t & 31;
    const int wid  = t >> 5;
    __shared__ int wsum[32];
    __shared__ int s_total;

    int mv[8];
    int cnt = 0;
    const int base_row = t * 8;
    #pragma unroll
    for (int r = 0; r < 8; r++) {
        mv[r] = mask[b * SS + base_row + r];
        cnt += (mv[r] != 0);
    }
    int x = cnt;
    #pragma unroll
    for (int off = 1; off < 32; off <<= 1) {
        int y = __shfl_up_sync(0xffffffffu, x, off);
        if (lane >= off) x += y;
    }
    if (lane == 31) wsum[wid] = x;
    const int excl = x - cnt;
    __syncthreads();
    if (t == 0) {
        int run = 0;
        for (int i = 0; i < 32; i++) { int c = wsum[i]; wsum[i] = run; run += c; }
        s_total = run;
    }
    __syncthreads();
    int base = wsum[wid] + excl;
    #pragma unroll
    for (int r = 0; r < 8; r++)
        if (mv[r]) g_rows[b][base++] = base_row + r;
    const int total = s_total;
    if (t == 0) g_cnt[b] = total;
    for (int i = total + t; i < SS; i += 1024) g_rows[b][i] = 0;   // pad
}

// ---------------------------------------------------------------------------
// Fused prep kernel (small now): qproj + Wk transpose/split.
//   blocks [0, 128)   : qproj (split-K x4)
//   blocks [128, 640) : prep_wk
// ---------------------------------------------------------------------------
__global__ __launch_bounds__(256)
void prep_fused_kernel(const float* __restrict__ query,
                       const float* __restrict__ Wq,
                       const float* __restrict__ Wk) {
    const int blk = blockIdx.x;
    const int t   = threadIdx.x;

    if (blk < 128) {
        // ---------------- qproj ----------------
        __shared__ float qs[AD];
        __shared__ float pred[4][64];
        const int b   = blk >> 3;            // 0..15
        const int seg = blk & 7;             // 0..7
        const int ci  = t & 63;
        const int kg  = t >> 6;
        const int col = seg * 64 + ci;

        for (int i = t; i < AD; i += 256) qs[i] = query[b * AD + i];
        __syncthreads();

        float acc = 0.f;
        const float* wcol = Wq + (size_t)(kg * 128) * AD + col;
        #pragma unroll 16
        for (int j = 0; j < 128; j++)
            acc += qs[kg * 128 + j] * wcol[(size_t)j * AD];
        pred[kg][ci] = acc;
        __syncthreads();
        if (t < 64)
            g_qp[b * AD + col] = pred[0][ci] + pred[1][ci] + pred[2][ci] + pred[3][ci];
    } else {
        // ---------------- prep_wk ----------------
        const int k = blk - 128;             // 0..511
        for (int n = t; n < AD; n += 256) {
            const float x = Wk[k * AD + n];
            const __nv_bfloat16 hi = __float2bfloat16(x);
            const __nv_bfloat16 lo = __float2bfloat16(x - __bfloat162float(hi));
            g_Bt_hi[n * KD + k] = hi;
            g_Bt_lo[n * KD + k] = lo;
        }
    }
}

// ---------------------------------------------------------------------------
// Kernel 2: bf16 3-term GEMM, in-kernel A gather+convert, SINGLE-stage smem,
//   2 CTAs/SM.  128x128 block, 8 warps (2M x 4N), warp 64x32.
//   B via cp.async (prepped bf16); A via LDG fp32 -> hi/lo CVT -> STS.
// ---------------------------------------------------------------------------
#define PADK 40                     // 80B row stride, ldmatrix conflict-free
#define ARR_B  (128 * PADK * 2)     // 10240 bytes per array
#define OFF_AH 0
#define OFF_AL ARR_B
#define OFF_BH (2 * ARR_B)
#define OFF_BL (3 * ARR_B)
#define SMEM_DYN (4 * ARR_B)        // 40960 per CTA; e_red overlays after loop

__global__ __launch_bounds__(256, 2)
void score_gemm_mma(const float* __restrict__ keys,
                    const float* __restrict__ vvec) {
    extern __shared__ char smem[];
    __shared__ int rows_s[128];
    const uint32_t sb = smem_u32(smem);

    const int tid = threadIdx.x;
    const int nt  = blockIdx.x;          // 0..3
    const int mt  = blockIdx.y;          // 0..1023
    const int b   = mt >> 6;
    const int tofs = (mt & 63) * 128;

    const int cnt = g_cnt[b];
    if (tofs >= cnt) return;

    const int wid = tid >> 5;
    const int lid = tid & 31;
    const int wm  = wid & 1;
    const int wn  = wid >> 1;

    if (tid < 128) rows_s[tid] = g_rows[b][tofs + tid];
    __syncthreads();

    // loader mapping: 512 granules per array (128 rows x 4 col-groups); 2/thread
    const int g0row = tid >> 2,  g0c = (tid & 3) * 8;
    const int g1row = g0row + 64;

    const float* aRow0 = keys + ((size_t)b * SS + rows_s[g0row]) * KD + g0c;
    const float* aRow1 = keys + ((size_t)b * SS + rows_s[g1row]) * KD + g0c;
    const __nv_bfloat16* BtH = g_Bt_hi + (size_t)(nt * 128) * KD;
    const __nv_bfloat16* BtL = g_Bt_lo + (size_t)(nt * 128) * KD;

    const uint32_t st0 = (uint32_t)(g0row * PADK + g0c) * 2;
    const uint32_t st1 = (uint32_t)(g1row * PADK + g0c) * 2;

    float acc[4][4][4];
    #pragma unroll
    for (int i = 0; i < 4; i++)
        #pragma unroll
        for (int j = 0; j < 4; j++)
            #pragma unroll
            for (int e = 0; e < 4; e++) acc[i][j][e] = 0.f;

    // fragment address components
    const int arow  = wm * 64 + (lid & 15);
    const int acolh = (lid >> 4) << 3;
    const int brow  = wn * 32 + ((lid >> 4) << 3) + (lid & 7);
    const int bcolh = ((lid >> 3) & 1) << 3;

    const uint32_t sAh = sb + OFF_AH;
    const uint32_t sAl = sb + OFF_AL;
    const uint32_t sBh = sb + OFF_BH;
    const uint32_t sBl = sb + OFF_BL;

    for (int kc = 0; kc < 16; kc++) {
        const int ko = kc * 32;
        // ---- B chunk via cp.async (4 x 16B per thread) ----
        CP_ASYNC16(sBh + st0, BtH + (size_t)g0row * KD + ko + g0c);
        CP_ASYNC16(sBh + st1, BtH + (size_t)g1row * KD + ko + g0c);
        CP_ASYNC16(sBl + st0, BtL + (size_t)g0row * KD + ko + g0c);
        CP_ASYNC16(sBl + st1, BtL + (size_t)g1row * KD + ko + g0c);
        CP_COMMIT();

        // ---- A chunk: gathered LDG fp32 -> hi/lo convert -> STS ----
        #pragma unroll
        for (int h = 0; h < 2; h++) {
            const float* src = (h ? aRow1 : aRow0) + ko;
            float4 f0 = *(const float4*)(src);
            float4 f1 = *(const float4*)(src + 4);
            const float xs[8] = {f0.x, f0.y, f0.z, f0.w, f1.x, f1.y, f1.z, f1.w};
            uint4 hv, lv;
            __nv_bfloat162* hp = (__nv_bfloat162*)&hv;
            __nv_bfloat162* lp = (__nv_bfloat162*)&lv;
            #pragma unroll
            for (int p = 0; p < 4; p++) {
                const float x0 = xs[2 * p], x1 = xs[2 * p + 1];
                const __nv_bfloat16 h0 = __float2bfloat16(x0);
                const __nv_bfloat16 h1 = __float2bfloat16(x1);
                const __nv_bfloat16 l0 = __float2bfloat16(x0 - __bfloat162float(h0));
                const __nv_bfloat16 l1 = __float2bfloat16(x1 - __bfloat162float(h1));
                hp[p] = __nv_bfloat162(h0, h1);
                lp[p] = __nv_bfloat162(l0, l1);
            }
            const uint32_t so = h ? st1 : st0;
            *(uint4*)(smem + OFF_AH + so) = hv;
            *(uint4*)(smem + OFF_AL + so) = lv;
        }
        CP_WAIT0();
        __syncthreads();                 // stage filled

        // ---- MMAs: 2 k-steps of k16; B frags resident, A frags per-mf ----
        #pragma unroll
        for (int ks = 0; ks < 2; ks++) {
            const int kb = ks * 16;
            uint32_t bh[4][2], bl[4][2];
            #pragma unroll
            for (int nf2 = 0; nf2 < 2; nf2++) {
                const uint32_t off = (uint32_t)(((brow + nf2 * 16) * PADK + kb + bcolh) * 2);
                uint32_t u[4];
                ldsm_x4(u, sBh + off);
                bh[2 * nf2][0] = u[0]; bh[2 * nf2][1] = u[1];
                bh[2 * nf2 + 1][0] = u[2]; bh[2 * nf2 + 1][1] = u[3];
                ldsm_x4(u, sBl + off);
                bl[2 * nf2][0] = u[0]; bl[2 * nf2][1] = u[1];
                bl[2 * nf2 + 1][0] = u[2]; bl[2 * nf2 + 1][1] = u[3];
            }
            #pragma unroll
            for (int mf = 0; mf < 4; mf++) {
                uint32_t ah[4], al[4];
                const uint32_t off = (uint32_t)(((arow + mf * 16) * PADK + kb + acolh) * 2);
                ldsm_x4(ah, sAh + off);
                ldsm_x4(al, sAl + off);
                #pragma unroll
                for (int nf = 0; nf < 4; nf++) {
                    mma16816(acc[mf][nf], ah, bh[nf]);
                    mma16816(acc[mf][nf], al, bh[nf]);
                    mma16816(acc[mf][nf], ah, bl[nf]);
                }
            }
        }
        __syncthreads();                 // all warps done before refill
    }

    // ---- epilogue: e_partial[row] = sum over this block's 128 cols ----
    float qv[4][2], vv[4][2];
    #pragma unroll
    for (int nf = 0; nf < 4; nf++)
        #pragma unroll
        for (int j = 0; j < 2; j++) {
            const int col = nt * 128 + wn * 32 + nf * 8 + (lid & 3) * 2 + j;
            qv[nf][j] = g_qp[b * AD + col];
            vv[nf][j] = vvec[col];
        }

    float es[4][2];
    #pragma unroll
    for (int mf = 0; mf < 4; mf++)
        #pragma unroll
        for (int h = 0; h < 2; h++) {
            float s = 0.f;
            #pragma unroll
            for (int nf = 0; nf < 4; nf++) {
                s += tanh_fast(acc[mf][nf][2 * h + 0] + qv[nf][0]) * vv[nf][0];
                s += tanh_fast(acc[mf][nf][2 * h + 1] + qv[nf][1]) * vv[nf][1];
            }
            es[mf][h] = s;
        }
    #pragma unroll
    for (int off = 1; off <= 2; off <<= 1)
        #pragma unroll
        for (int mf = 0; mf < 4; mf++)
            #pragma unroll
            for (int h = 0; h < 2; h++)
                es[mf][h] += __shfl_xor_sync(0xffffffffu, es[mf][h], off);

    float (*e_red)[128] = (float (*)[128])(smem);    // overlay stage (free now)
    if ((lid & 3) == 0) {
        const int gq = lid >> 2;
        #pragma unroll
        for (int mf = 0; mf < 4; mf++)
            #pragma unroll
            for (int h = 0; h < 2; h++)
                e_red[wn][wm * 64 + mf * 16 + h * 8 + gq] = es[mf][h];
    }
    __syncthreads();
    if (tid < 128)
        g_epart[nt * MTOT + b * SS + tofs + tid] =
            e_red[0][tid] + e_red[1][tid] + e_red[2][tid] + e_red[3][tid];
}

// ---------------------------------------------------------------------------
// Kernel 3: softmax over compacted scores; scatter a + zero masked slots
// ---------------------------------------------------------------------------
__global__ __launch_bounds__(1024)
void softmax_kernel(const int* __restrict__ mask, float* __restrict__ out) {
    const int b = blockIdx.x;
    const int t = threadIdx.x;
    const int lane = t & 31;
    const int wid  = t >> 5;
    __shared__ float sred[32];

    const int cnt = g_cnt[b];

    float sc[8];
    #pragma unroll
    for (int r = 0; r < 8; r++) {
        const int i = t + r * 1024;
        float e = -FLT_MAX;
        if (i < cnt) {
            e = 0.f;
            #pragma unroll
            for (int p = 0; p < NT; p++)
                e += g_epart[p * MTOT + b * SS + i];
        }
        sc[r] = e;
    }

    float m = sc[0];
    #pragma unroll
    for (int r = 1; r < 8; r++) m = fmaxf(m, sc[r]);
    #pragma unroll
    for (int off = 16; off > 0; off >>= 1)
        m = fmaxf(m, __shfl_xor_sync(0xffffffffu, m, off));
    if (lane == 0) sred[wid] = m;
    __syncthreads();
    if (t < 32) {
        float x = sred[t];
        #pragma unroll
        for (int off = 16; off > 0; off >>= 1)
            x = fmaxf(x, __shfl_xor_sync(0xffffffffu, x, off));
        if (t == 0) sred[0] = x;
    }
    __syncthreads();
    m = sred[0];
    __syncthreads();

    float ex[8];
    float sum = 0.f;
    #pragma unroll
    for (int r = 0; r < 8; r++) {
        ex[r] = expf(sc[r] - m);
        sum += ex[r];
    }
    #pragma unroll
    for (int off = 16; off > 0; off >>= 1)
        sum += __shfl_xor_sync(0xffffffffu, sum, off);
    if (lane == 0) sred[wid] = sum;
    __syncthreads();
    if (t < 32) {
        float x = sred[t];
        #pragma unroll
        for (int off = 16; off > 0; off >>= 1)
            x += __shfl_xor_sync(0xffffffffu, x, off);
        if (t == 0) sred[0] = x;
    }
    __syncthreads();
    const float inv = 1.f / sred[0];

    #pragma unroll
    for (int r = 0; r < 8; r++) {
        const int i = t + r * 1024;
        const float av = (i < cnt) ? ex[r] * inv : 0.f;
        g_acomp[b][i] = av;
        if (i < cnt) out[BB * KD + b * SS + g_rows[b][i]] = av;
        if (mask[b * SS + i] == 0) out[BB * KD + b * SS + i] = 0.f;
    }
}

// ---------------------------------------------------------------------------
// Kernel 4: context partials over compacted rows (gathered keys)
// ---------------------------------------------------------------------------
__global__ __launch_bounds__(256)
void ctx_part_kernel(const float* __restrict__ keys) {
    const int scn = blockIdx.x;
    const int b   = blockIdx.y;
    const int t   = threadIdx.x;

    if (scn * 128 >= g_cnt[b]) {
        g_cpart[(scn * BB + b) * KD + t]       = 0.f;
        g_cpart[(scn * BB + b) * KD + t + 256] = 0.f;
        return;
    }

    __shared__ float as[128];
    __shared__ int   rs[128];
    if (t < 128) {
        as[t] = g_acomp[b][scn * 128 + t];
        rs[t] = g_rows[b][scn * 128 + t];
    }
    __syncthreads();

    const float* kb = keys + (size_t)b * SS * KD;
    float s0 = 0.f, s1 = 0.f;
    #pragma unroll 4
    for (int s = 0; s < 128; s++) {
        const float av = as[s];
        const float* kr = kb + (size_t)rs[s] * KD;
        s0 += av * kr[t];
        s1 += av * kr[t + 256];
    }
    g_cpart[(scn * BB + b) * KD + t]       = s0;
    g_cpart[(scn * BB + b) * KD + t + 256] = s1;
}

// ---------------------------------------------------------------------------
// Kernel 5: reduce context partials
// ---------------------------------------------------------------------------
__global__ __launch_bounds__(512)
void ctx_reduce_kernel(float* __restrict__ out) {
    const int b = blockIdx.x;
    const int t = threadIdx.x;
    float s = 0.f;
    #pragma unroll 8
    for (int scn = 0; scn < 64; scn++)
        s += g_cpart[(scn * BB + b) * KD + t];
    out[b * KD + t] = s;
}

// ---------------------------------------------------------------------------
extern "C" void kernel_launch(void* const* d_in, const int* in_sizes, int n_in,
                              void* d_out, int out_size) {
    const float* query = (const float*)d_in[0];
    const float* keys  = (const float*)d_in[1];
    const int*   mask  = (const int*)  d_in[2];
    const float* Wq    = (const float*)d_in[3];
    const float* Wk    = (const float*)d_in[4];
    const float* v     = (const float*)d_in[5];
    float* out = (float*)d_out;

    static bool attr_set = false;
    if (!attr_set) {
        cudaFuncSetAttribute(score_gemm_mma,
                             cudaFuncAttributeMaxDynamicSharedMemorySize, SMEM_DYN);
        attr_set = true;
    }

    compact_kernel<<<BB, 1024>>>(mask);
    prep_fused_kernel<<<640, 256>>>(query, Wq, Wk);
    score_gemm_mma<<<dim3(NT, 1024), 256, SMEM_DYN>>>(keys, v);
    softmax_kernel<<<BB, 1024>>>(mask, out);
    ctx_part_kernel<<<dim3(64, BB), 256>>>(keys);
    ctx_reduce_kernel<<<BB, 512>>>(out);
}

// round 15
// speedup vs baseline: 1.2976x; 1.0684x over previous
#include <cuda_runtime.h>
#include <cuda_bf16.h>
#include <cfloat>
#include <math.h>
#include <cstdint>

// Problem constants
#define BB   16
#define SS   8192
#define AD   512
#define KD   512
#define MTOT (BB * SS)
#define NT   4          // 4 N-tiles of 128 cols

// ---------------------------------------------------------------------------
// Scratch globals
// ---------------------------------------------------------------------------
__device__ float         g_qp[BB * AD];
__device__ float         g_epart[NT * MTOT];
__device__ float         g_cpart[64 * BB * KD];
__device__ __nv_bfloat16 g_Bt_hi[AD * KD];    // n-major: [n][k] = hi(Wk[k][n])
__device__ __nv_bfloat16 g_Bt_lo[AD * KD];
__device__ int           g_rows[BB][SS];      // compacted active row indices
__device__ int           g_cnt[BB];           // active counts
__device__ float         g_acomp[BB][SS];     // compacted attention weights

// ---------------------------------------------------------------------------
// PTX helpers
// ---------------------------------------------------------------------------
__device__ __forceinline__ float tanh_fast(float x) {
    float y;
    asm("tanh.approx.f32 %0, %1;" : "=f"(y) : "f"(x));
    return y;
}
__device__ __forceinline__ uint32_t smem_u32(const void* p) {
    uint32_t a;
    asm("{ .reg .u64 t; cvta.to.shared.u64 t, %1; cvt.u32.u64 %0, t; }" : "=r"(a) : "l"(p));
    return a;
}
__device__ __forceinline__ void ldsm_x4(uint32_t* r, uint32_t addr) {
    asm volatile("ldmatrix.sync.aligned.m8n8.x4.shared.b16 {%0,%1,%2,%3}, [%4];"
                 : "=r"(r[0]), "=r"(r[1]), "=r"(r[2]), "=r"(r[3]) : "r"(addr));
}
__device__ __forceinline__ void mma16816(float* d, const uint32_t* a, const uint32_t* b) {
    asm volatile(
        "mma.sync.aligned.m16n8k16.row.col.f32.bf16.bf16.f32 "
        "{%0,%1,%2,%3}, {%4,%5,%6,%7}, {%8,%9}, {%0,%1,%2,%3};"
        : "+f"(d[0]), "+f"(d[1]), "+f"(d[2]), "+f"(d[3])
        : "r"(a[0]), "r"(a[1]), "r"(a[2]), "r"(a[3]), "r"(b[0]), "r"(b[1]));
}
#define CP_ASYNC16(dst, src) \
    asm volatile("cp.async.cg.shared.global [%0], [%1], 16;" :: "r"(dst), "l"(src) : "memory")
#define CP_COMMIT()  asm volatile("cp.async.commit_group;" ::: "memory")
#define CP_WAIT0()   asm volatile("cp.async.wait_group 0;" ::: "memory")

// ---------------------------------------------------------------------------
// Kernel A: per-batch stable compaction of active rows (mask != 0)
// ---------------------------------------------------------------------------
__global__ __launch_bounds__(1024)
void compact_kernel(const int* __restrict__ mask) {
    const int b = blockIdx.x;
    const int t = threadIdx.x;
    const int lane = t & 31;
    const int wid  = t >> 5;
    __shared__ int wsum[32];
    __shared__ int s_total;

    int mv[8];
    int cnt = 0;
    const int base_row = t * 8;
    #pragma unroll
    for (int r = 0; r < 8; r++) {
        mv[r] = mask[b * SS + base_row + r];
        cnt += (mv[r] != 0);
    }
    int x = cnt;
    #pragma unroll
    for (int off = 1; off < 32; off <<= 1) {
        int y = __shfl_up_sync(0xffffffffu, x, off);
        if (lane >= off) x += y;
    }
    if (lane == 31) wsum[wid] = x;
    const int excl = x - cnt;
    __syncthreads();
    if (t == 0) {
        int run = 0;
        for (int i = 0; i < 32; i++) { int c = wsum[i]; wsum[i] = run; run += c; }
        s_total = run;
    }
    __syncthreads();
    int base = wsum[wid] + excl;
    #pragma unroll
    for (int r = 0; r < 8; r++)
        if (mv[r]) g_rows[b][base++] = base_row + r;
    const int total = s_total;
    if (t == 0) g_cnt[b] = total;
    for (int i = total + t; i < SS; i += 1024) g_rows[b][i] = 0;   // pad
}

// ---------------------------------------------------------------------------
// Fused prep kernel: qproj + Wk transpose/split.
//   blocks [0, 128)   : qproj (split-K x4)
//   blocks [128, 640) : prep_wk
// ---------------------------------------------------------------------------
__global__ __launch_bounds__(256)
void prep_fused_kernel(const float* __restrict__ query,
                       const float* __restrict__ Wq,
                       const float* __restrict__ Wk) {
    const int blk = blockIdx.x;
    const int t   = threadIdx.x;

    if (blk < 128) {
        // ---------------- qproj ----------------
        __shared__ float qs[AD];
        __shared__ float pred[4][64];
        const int b   = blk >> 3;            // 0..15
        const int seg = blk & 7;             // 0..7
        const int ci  = t & 63;
        const int kg  = t >> 6;
        const int col = seg * 64 + ci;

        for (int i = t; i < AD; i += 256) qs[i] = query[b * AD + i];
        __syncthreads();

        float acc = 0.f;
        const float* wcol = Wq + (size_t)(kg * 128) * AD + col;
        #pragma unroll 16
        for (int j = 0; j < 128; j++)
            acc += qs[kg * 128 + j] * wcol[(size_t)j * AD];
        pred[kg][ci] = acc;
        __syncthreads();
        if (t < 64)
            g_qp[b * AD + col] = pred[0][ci] + pred[1][ci] + pred[2][ci] + pred[3][ci];
    } else {
        // ---------------- prep_wk ----------------
        const int k = blk - 128;             // 0..511
        for (int n = t; n < AD; n += 256) {
            const float x = Wk[k * AD + n];
            const __nv_bfloat16 hi = __float2bfloat16(x);
            const __nv_bfloat16 lo = __float2bfloat16(x - __bfloat162float(hi));
            g_Bt_hi[n * KD + k] = hi;
            g_Bt_lo[n * KD + k] = lo;
        }
    }
}

// ---------------------------------------------------------------------------
// Kernel 2: bf16 3-term GEMM, in-kernel A gather+convert, 2-STAGE buffer AND
//   2 CTAs/SM (163.8 KB smem total).  128x128 block, 8 warps (2M x 4N).
//   Per chunk: issue B cp.async + A LDG for next stage, MMA current, then
//   convert+STS A, wait, ONE sync.
// ---------------------------------------------------------------------------
#define PADK 40                     // 80B row stride, ldmatrix conflict-free
#define ARR_B  (128 * PADK * 2)     // 10240 bytes per array
#define STG_B  (4 * ARR_B)          // 40960 bytes per stage
#define OFF_AH 0
#define OFF_AL ARR_B
#define OFF_BH (2 * ARR_B)
#define OFF_BL (3 * ARR_B)
#define SMEM_DYN (2 * STG_B)        // 81920 per CTA; 2 CTAs = 163840/SM

__global__ __launch_bounds__(256, 2)
void score_gemm_mma(const float* __restrict__ keys,
                    const float* __restrict__ vvec) {
    extern __shared__ char smem[];
    __shared__ int rows_s[128];
    const uint32_t sb = smem_u32(smem);

    const int tid = threadIdx.x;
    const int nt  = blockIdx.x;          // 0..3
    const int mt  = blockIdx.y;          // 0..1023
    const int b   = mt >> 6;
    const int tofs = (mt & 63) * 128;

    const int cnt = g_cnt[b];
    if (tofs >= cnt) return;

    const int wid = tid >> 5;
    const int lid = tid & 31;
    const int wm  = wid & 1;
    const int wn  = wid >> 1;

    if (tid < 128) rows_s[tid] = g_rows[b][tofs + tid];
    __syncthreads();

    // loader mapping: 512 granules per array (128 rows x 4 col-groups); 2/thread
    const int g0row = tid >> 2,  g0c = (tid & 3) * 8;
    const int g1row = g0row + 64;

    const float* aRow0 = keys + ((size_t)b * SS + rows_s[g0row]) * KD + g0c;
    const float* aRow1 = keys + ((size_t)b * SS + rows_s[g1row]) * KD + g0c;
    const __nv_bfloat16* BtH = g_Bt_hi + (size_t)(nt * 128) * KD;
    const __nv_bfloat16* BtL = g_Bt_lo + (size_t)(nt * 128) * KD;

    const uint32_t st0 = (uint32_t)(g0row * PADK + g0c) * 2;
    const uint32_t st1 = (uint32_t)(g1row * PADK + g0c) * 2;

    float4 pa[4];                        // prefetched A fp32 (next chunk)

    auto loadA = [&](int ko) {
        pa[0] = *(const float4*)(aRow0 + ko);
        pa[1] = *(const float4*)(aRow0 + ko + 4);
        pa[2] = *(const float4*)(aRow1 + ko);
        pa[3] = *(const float4*)(aRow1 + ko + 4);
    };
    auto storeA = [&](uint32_t stage_byte_off) {
        #pragma unroll
        for (int h = 0; h < 2; h++) {
            const float* xs = (const float*)&pa[h * 2];
            uint4 hv, lv;
            __nv_bfloat162* hp = (__nv_bfloat162*)&hv;
            __nv_bfloat162* lp = (__nv_bfloat162*)&lv;
            #pragma unroll
            for (int p = 0; p < 4; p++) {
                const float x0 = xs[2 * p], x1 = xs[2 * p + 1];
                const __nv_bfloat16 h0 = __float2bfloat16(x0);
                const __nv_bfloat16 h1 = __float2bfloat16(x1);
                const __nv_bfloat16 l0 = __float2bfloat16(x0 - __bfloat162float(h0));
                const __nv_bfloat16 l1 = __float2bfloat16(x1 - __bfloat162float(h1));
                hp[p] = __nv_bfloat162(h0, h1);
                lp[p] = __nv_bfloat162(l0, l1);
            }
            const uint32_t so = h ? st1 : st0;
            *(uint4*)(smem + stage_byte_off + OFF_AH + so) = hv;
            *(uint4*)(smem + stage_byte_off + OFF_AL + so) = lv;
        }
    };
    auto issueB = [&](uint32_t stage_u32, int ko) {
        CP_ASYNC16(stage_u32 + OFF_BH + st0, BtH + (size_t)g0row * KD + ko + g0c);
        CP_ASYNC16(stage_u32 + OFF_BH + st1, BtH + (size_t)g1row * KD + ko + g0c);
        CP_ASYNC16(stage_u32 + OFF_BL + st0, BtL + (size_t)g0row * KD + ko + g0c);
        CP_ASYNC16(stage_u32 + OFF_BL + st1, BtL + (size_t)g1row * KD + ko + g0c);
        CP_COMMIT();
    };

    float acc[4][4][4];
    #pragma unroll
    for (int i = 0; i < 4; i++)
        #pragma unroll
        for (int j = 0; j < 4; j++)
            #pragma unroll
            for (int e = 0; e < 4; e++) acc[i][j][e] = 0.f;

    // fragment address components
    const int arow  = wm * 64 + (lid & 15);
    const int acolh = (lid >> 4) << 3;
    const int brow  = wn * 32 + ((lid >> 4) << 3) + (lid & 7);
    const int bcolh = ((lid >> 3) & 1) << 3;

    // ---- prologue: fill stage 0 ----
    issueB(sb, 0);
    loadA(0);
    storeA(0);
    CP_WAIT0();
    __syncthreads();

    for (int kc = 0; kc < 16; kc++) {
        const uint32_t curb = (uint32_t)(kc & 1) * STG_B;
        const uint32_t nxtb = curb ^ STG_B;

        // issue next-stage loads before MMA (latency covered by MMA below)
        if (kc + 1 < 16) {
            issueB(sb + nxtb, (kc + 1) * 32);
            loadA((kc + 1) * 32);
        }

        const uint32_t sAh = sb + curb + OFF_AH;
        const uint32_t sAl = sb + curb + OFF_AL;
        const uint32_t sBh = sb + curb + OFF_BH;
        const uint32_t sBl = sb + curb + OFF_BL;

        #pragma unroll
        for (int ks = 0; ks < 2; ks++) {
            const int kb = ks * 16;
            uint32_t bh[4][2], bl[4][2];
            #pragma unroll
            for (int nf2 = 0; nf2 < 2; nf2++) {
                const uint32_t off = (uint32_t)(((brow + nf2 * 16) * PADK + kb + bcolh) * 2);
                uint32_t u[4];
                ldsm_x4(u, sBh + off);
                bh[2 * nf2][0] = u[0]; bh[2 * nf2][1] = u[1];
                bh[2 * nf2 + 1][0] = u[2]; bh[2 * nf2 + 1][1] = u[3];
                ldsm_x4(u, sBl + off);
                bl[2 * nf2][0] = u[0]; bl[2 * nf2][1] = u[1];
                bl[2 * nf2 + 1][0] = u[2]; bl[2 * nf2 + 1][1] = u[3];
            }
            #pragma unroll
            for (int mf = 0; mf < 4; mf++) {
                uint32_t ah[4], al[4];
                const uint32_t off = (uint32_t)(((arow + mf * 16) * PADK + kb + acolh) * 2);
                ldsm_x4(ah, sAh + off);
                ldsm_x4(al, sAl + off);
                #pragma unroll
                for (int nf = 0; nf < 4; nf++) {
                    mma16816(acc[mf][nf], ah, bh[nf]);
                    mma16816(acc[mf][nf], al, bh[nf]);
                    mma16816(acc[mf][nf], ah, bl[nf]);
                }
            }
        }

        // convert+store prefetched A into next stage; wait for its B; one sync
        if (kc + 1 < 16) {
            storeA(nxtb);
            CP_WAIT0();
        }
        __syncthreads();
    }

    // ---- epilogue: e_partial[row] = sum over this block's 128 cols ----
    float qv[4][2], vv[4][2];
    #pragma unroll
    for (int nf = 0; nf < 4; nf++)
        #pragma unroll
        for (int j = 0; j < 2; j++) {
            const int col = nt * 128 + wn * 32 + nf * 8 + (lid & 3) * 2 + j;
            qv[nf][j] = g_qp[b * AD + col];
            vv[nf][j] = vvec[col];
        }

    float es[4][2];
    #pragma unroll
    for (int mf = 0; mf < 4; mf++)
        #pragma unroll
        for (int h = 0; h < 2; h++) {
            float s = 0.f;
            #pragma unroll
            for (int nf = 0; nf < 4; nf++) {
                s += tanh_fast(acc[mf][nf][2 * h + 0] + qv[nf][0]) * vv[nf][0];
                s += tanh_fast(acc[mf][nf][2 * h + 1] + qv[nf][1]) * vv[nf][1];
            }
            es[mf][h] = s;
        }
    #pragma unroll
    for (int off = 1; off <= 2; off <<= 1)
        #pragma unroll
        for (int mf = 0; mf < 4; mf++)
            #pragma unroll
            for (int h = 0; h < 2; h++)
                es[mf][h] += __shfl_xor_sync(0xffffffffu, es[mf][h], off);

    float (*e_red)[128] = (float (*)[128])(smem);    // overlay stage 0 (free now)
    if ((lid & 3) == 0) {
        const int gq = lid >> 2;
        #pragma unroll
        for (int mf = 0; mf < 4; mf++)
            #pragma unroll
            for (int h = 0; h < 2; h++)
                e_red[wn][wm * 64 + mf * 16 + h * 8 + gq] = es[mf][h];
    }
    __syncthreads();
    if (tid < 128)
        g_epart[nt * MTOT + b * SS + tofs + tid] =
            e_red[0][tid] + e_red[1][tid] + e_red[2][tid] + e_red[3][tid];
}

// ---------------------------------------------------------------------------
// Kernel 3: softmax over compacted scores; scatter a + zero masked slots
// ---------------------------------------------------------------------------
__global__ __launch_bounds__(1024)
void softmax_kernel(const int* __restrict__ mask, float* __restrict__ out) {
    const int b = blockIdx.x;
    const int t = threadIdx.x;
    const int lane = t & 31;
    const int wid  = t >> 5;
    __shared__ float sred[32];

    const int cnt = g_cnt[b];

    float sc[8];
    #pragma unroll
    for (int r = 0; r < 8; r++) {
        const int i = t + r * 1024;
        float e = -FLT_MAX;
        if (i < cnt) {
            e = 0.f;
            #pragma unroll
            for (int p = 0; p < NT; p++)
                e += g_epart[p * MTOT + b * SS + i];
        }
        sc[r] = e;
    }

    float m = sc[0];
    #pragma unroll
    for (int r = 1; r < 8; r++) m = fmaxf(m, sc[r]);
    #pragma unroll
    for (int off = 16; off > 0; off >>= 1)
        m = fmaxf(m, __shfl_xor_sync(0xffffffffu, m, off));
    if (lane == 0) sred[wid] = m;
    __syncthreads();
    if (t < 32) {
        float x = sred[t];
        #pragma unroll
        for (int off = 16; off > 0; off >>= 1)
            x = fmaxf(x, __shfl_xor_sync(0xffffffffu, x, off));
        if (t == 0) sred[0] = x;
    }
    __syncthreads();
    m = sred[0];
    __syncthreads();

    float ex[8];
    float sum = 0.f;
    #pragma unroll
    for (int r = 0; r < 8; r++) {
        ex[r] = expf(sc[r] - m);
        sum += ex[r];
    }
    #pragma unroll
    for (int off = 16; off > 0; off >>= 1)
        sum += __shfl_xor_sync(0xffffffffu, sum, off);
    if (lane == 0) sred[wid] = sum;
    __syncthreads();
    if (t < 32) {
        float x = sred[t];
        #pragma unroll
        for (int off = 16; off > 0; off >>= 1)
            x += __shfl_xor_sync(0xffffffffu, x, off);
        if (t == 0) sred[0] = x;
    }
    __syncthreads();
    const float inv = 1.f / sred[0];

    #pragma unroll
    for (int r = 0; r < 8; r++) {
        const int i = t + r * 1024;
        const float av = (i < cnt) ? ex[r] * inv : 0.f;
        g_acomp[b][i] = av;
        if (i < cnt) out[BB * KD + b * SS + g_rows[b][i]] = av;
        if (mask[b * SS + i] == 0) out[BB * KD + b * SS + i] = 0.f;
    }
}

// ---------------------------------------------------------------------------
// Kernel 4: context partials over compacted rows (gathered keys)
// ---------------------------------------------------------------------------
__global__ __launch_bounds__(256)
void ctx_part_kernel(const float* __restrict__ keys) {
    const int scn = blockIdx.x;
    const int b   = blockIdx.y;
    const int t   = threadIdx.x;

    if (scn * 128 >= g_cnt[b]) {
        g_cpart[(scn * BB + b) * KD + t]       = 0.f;
        g_cpart[(scn * BB + b) * KD + t + 256] = 0.f;
        return;
    }

    __shared__ float as[128];
    __shared__ int   rs[128];
    if (t < 128) {
        as[t] = g_acomp[b][scn * 128 + t];
        rs[t] = g_rows[b][scn * 128 + t];
    }
    __syncthreads();

    const float* kb = keys + (size_t)b * SS * KD;
    float s0 = 0.f, s1 = 0.f;
    #pragma unroll 4
    for (int s = 0; s < 128; s++) {
        const float av = as[s];
        const float* kr = kb + (size_t)rs[s] * KD;
        s0 += av * kr[t];
        s1 += av * kr[t + 256];
    }
    g_cpart[(scn * BB + b) * KD + t]       = s0;
    g_cpart[(scn * BB + b) * KD + t + 256] = s1;
}

// ---------------------------------------------------------------------------
// Kernel 5: reduce context partials
// ---------------------------------------------------------------------------
__global__ __launch_bounds__(512)
void ctx_reduce_kernel(float* __restrict__ out) {
    const int b = blockIdx.x;
    const int t = threadIdx.x;
    float s = 0.f;
    #pragma unroll 8
    for (int scn = 0; scn < 64; scn++)
        s += g_cpart[(scn * BB + b) * KD + t];
    out[b * KD + t] = s;
}

// ---------------------------------------------------------------------------
extern "C" void kernel_launch(void* const* d_in, const int* in_sizes, int n_in,
                              void* d_out, int out_size) {
    const float* query = (const float*)d_in[0];
    const float* keys  = (const float*)d_in[1];
    const int*   mask  = (const int*)  d_in[2];
    const float* Wq    = (const float*)d_in[3];
    const float* Wk    = (const float*)d_in[4];
    const float* v     = (const float*)d_in[5];
    float* out = (float*)d_out;

    static bool attr_set = false;
    if (!attr_set) {
        cudaFuncSetAttribute(score_gemm_mma,
                             cudaFuncAttributeMaxDynamicSharedMemorySize, SMEM_DYN);
        attr_set = true;
    }

    compact_kernel<<<BB, 1024>>>(mask);
    prep_fused_kernel<<<640, 256>>>(query, Wq, Wk);
    score_gemm_mma<<<dim3(NT, 1024), 256, SMEM_DYN>>>(keys, v);
    softmax_kernel<<<BB, 1024>>>(mask, out);
    ctx_part_kernel<<<dim3(64, BB), 256>>>(keys);
    ctx_reduce_kernel<<<BB, 512>>>(out);
}